// round 3
// baseline (speedup 1.0000x reference)
#include <cuda_runtime.h>
#include <cuda_bf16.h>

#define NNODES   50000
#define ETOT_MAX 900000
#define FIN      128
#define HID      256
#define NHEAD    8

// ---------------- scratch (static device globals; no allocation) ----------------
__device__ int   g_rowptr[NNODES + 1];
__device__ int   g_cursor[NNODES];
__device__ int   g_srcs[ETOT_MAX];
__device__ __align__(16) float g_h[NNODES * HID];   // transformed features of current layer
__device__ __align__(16) float g_x1[NNODES * HID];  // layer-1 output (input of layer 2)
__device__ float g_als[NNODES * NHEAD];
__device__ float g_ald[NNODES * NHEAD];

// ---------------- CSR build ----------------
__global__ void zero_counts_kernel() {
    int i = blockIdx.x * blockDim.x + threadIdx.x;
    if (i <= NNODES) g_rowptr[i] = 0;
}

__global__ void hist_kernel(const int* __restrict__ dst, int etot) {
    int i = blockIdx.x * blockDim.x + threadIdx.x;
    if (i < etot) atomicAdd(&g_rowptr[dst[i]], 1);
}

// single-block exclusive scan over g_rowptr[0..N), writes g_rowptr (exclusive),
// g_cursor (copy), g_rowptr[N] = total
__global__ void scan_kernel() {
    __shared__ int sh[1024];
    int t = threadIdx.x;
    int carry = 0;
    for (int base = 0; base < NNODES; base += 1024) {
        int i = base + t;
        int v = (i < NNODES) ? g_rowptr[i] : 0;
        sh[t] = v;
        __syncthreads();
        #pragma unroll
        for (int off = 1; off < 1024; off <<= 1) {
            int x = (t >= off) ? sh[t - off] : 0;
            __syncthreads();
            sh[t] += x;
            __syncthreads();
        }
        int incl = sh[t];
        int excl = incl - v + carry;
        if (i < NNODES) { g_rowptr[i] = excl; g_cursor[i] = excl; }
        carry += sh[1023];
        __syncthreads();
    }
    if (t == 0) g_rowptr[NNODES] = carry;
}

__global__ void scatter_kernel(const int* __restrict__ src,
                               const int* __restrict__ dst, int etot) {
    int i = blockIdx.x * blockDim.x + threadIdx.x;
    if (i < etot) {
        int d = dst[i];
        int pos = atomicAdd(&g_cursor[d], 1);
        g_srcs[pos] = src[i];
    }
}

// ---------------- SGEMM: C[M,256] = A[M,K] * B[K,256] ----------------
// layer_sel: 0 -> A = Aext (x input), 1 -> A = g_x1. C = g_h always.
__global__ void __launch_bounds__(256)
sgemm_kernel(const float* __restrict__ Aext, const float* __restrict__ B,
             int M, int K, int layer_sel) {
    const float* __restrict__ A = layer_sel ? g_x1 : Aext;
    float* __restrict__ C = g_h;

    __shared__ float As[8][128];
    __shared__ float Bs[8][128];

    int tid = threadIdx.x;
    int tx = tid & 15;        // 0..15
    int ty = tid >> 4;        // 0..15
    int row0 = blockIdx.x * 128;
    int col0 = blockIdx.y * 128;

    float acc[8][8];
    #pragma unroll
    for (int i = 0; i < 8; i++)
        #pragma unroll
        for (int j = 0; j < 8; j++) acc[i][j] = 0.f;

    for (int k0 = 0; k0 < K; k0 += 8) {
        #pragma unroll
        for (int i = 0; i < 4; i++) {
            int idx = tid + 256 * i;      // 0..1023
            int r = idx >> 3, c = idx & 7;
            int gr = row0 + r;
            As[c][r] = (gr < M) ? A[(long)gr * K + k0 + c] : 0.f;
        }
        #pragma unroll
        for (int i = 0; i < 2; i++) {
            int idx = tid + 256 * i;      // 0..511
            int kr = idx >> 7, cc = idx & 127;
            Bs[kr][cc] = B[(k0 + kr) * HID + col0 + cc];
            Bs[kr + 4][cc] = B[(k0 + kr + 4) * HID + col0 + cc];
        }
        __syncthreads();

        #pragma unroll
        for (int kk = 0; kk < 8; kk++) {
            float a[8], b[8];
            #pragma unroll
            for (int i = 0; i < 8; i++) a[i] = As[kk][ty * 8 + i];
            #pragma unroll
            for (int j = 0; j < 8; j++) b[j] = Bs[kk][tx * 8 + j];
            #pragma unroll
            for (int i = 0; i < 8; i++)
                #pragma unroll
                for (int j = 0; j < 8; j++)
                    acc[i][j] = fmaf(a[i], b[j], acc[i][j]);
        }
        __syncthreads();
    }

    #pragma unroll
    for (int i = 0; i < 8; i++) {
        int gr = row0 + ty * 8 + i;
        if (gr < M) {
            #pragma unroll
            for (int j = 0; j < 8; j++)
                C[(long)gr * HID + col0 + tx * 8 + j] = acc[i][j];
        }
    }
}

// ---------------- attention logits: als/ald[v][h] = sum_c h[v][h*32+c]*a[h][c] ----------------
__global__ void __launch_bounds__(256)
al_kernel(const float* __restrict__ asrc, const float* __restrict__ adst) {
    int v = blockIdx.x;
    int tid = threadIdx.x, lane = tid & 31, warp = tid >> 5; // warp == head
    float hv = g_h[v * HID + tid];
    float ps = hv * asrc[tid];
    float pd = hv * adst[tid];
    #pragma unroll
    for (int o = 16; o; o >>= 1) {
        ps += __shfl_xor_sync(0xffffffffu, ps, o);
        pd += __shfl_xor_sync(0xffffffffu, pd, o);
    }
    if (lane == 0) {
        g_als[v * NHEAD + warp] = ps;
        g_ald[v * NHEAD + warp] = pd;
    }
}

// ---------------- segmented softmax + aggregation + bias + ELU ----------------
// one CTA (256 thr) per dst node. warp == head for logit work.
// use_internal: 1 -> write g_x1 (layer 1), 0 -> write outp (layer 2 / d_out)
__global__ void __launch_bounds__(256)
gat_agg_kernel(const float* __restrict__ bias, float* __restrict__ outp,
               int use_internal) {
    int v = blockIdx.x;
    int tid = threadIdx.x, lane = tid & 31, warp = tid >> 5;
    int start = g_rowptr[v], end = g_rowptr[v + 1];

    __shared__ float sh_m[8], sh_s[8];
    __shared__ float sh_w[8][64];
    __shared__ int   sh_src[64];
    __shared__ float4 sh_red[256];

    float aldv = g_ald[v * NHEAD + warp];

    // phase 1: per-head max over incoming edges
    float m = -1e30f;
    for (int j = start + lane; j < end; j += 32) {
        int s = g_srcs[j];
        float e = g_als[s * NHEAD + warp] + aldv;
        e = (e > 0.f) ? e : 0.2f * e;
        m = fmaxf(m, e);
    }
    #pragma unroll
    for (int o = 16; o; o >>= 1) m = fmaxf(m, __shfl_xor_sync(0xffffffffu, m, o));
    if (lane == 0) sh_m[warp] = m;
    __syncthreads();
    m = sh_m[warp];

    // phase 2+3: tiles of 64 edges -> exp weights in smem, weighted gather of h[src]
    float ssum = 0.f;
    float4 acc = make_float4(0.f, 0.f, 0.f, 0.f);
    int cg = tid & 63;          // channel group (4 ch each)
    int sub = tid >> 6;         // which of 4 concurrent edges
    int headc = cg >> 3;        // head owning these channels

    for (int t = start; t < end; t += 64) {
        int cnt = min(64, end - t);
        for (int j = lane; j < cnt; j += 32) {
            int s = g_srcs[t + j];
            if (warp == 0) sh_src[j] = s;
            float e = g_als[s * NHEAD + warp] + aldv;
            e = (e > 0.f) ? e : 0.2f * e;
            float w = __expf(e - m);
            sh_w[warp][j] = w;
            ssum += w;
        }
        __syncthreads();
        for (int j = sub; j < cnt; j += 4) {
            int s = sh_src[j];
            float w = sh_w[headc][j];
            const float4 hv = *reinterpret_cast<const float4*>(&g_h[s * HID + cg * 4]);
            acc.x = fmaf(w, hv.x, acc.x);
            acc.y = fmaf(w, hv.y, acc.y);
            acc.z = fmaf(w, hv.z, acc.z);
            acc.w = fmaf(w, hv.w, acc.w);
        }
        __syncthreads();
    }

    #pragma unroll
    for (int o = 16; o; o >>= 1) ssum += __shfl_xor_sync(0xffffffffu, ssum, o);
    if (lane == 0) sh_s[warp] = ssum;

    sh_red[tid] = acc;
    __syncthreads();

    if (tid < 64) {
        float4 a0 = sh_red[tid];
        float4 a1 = sh_red[tid + 64];
        float4 a2 = sh_red[tid + 128];
        float4 a3 = sh_red[tid + 192];
        float r0 = a0.x + a1.x + a2.x + a3.x;
        float r1 = a0.y + a1.y + a2.y + a3.y;
        float r2 = a0.z + a1.z + a2.z + a3.z;
        float r3 = a0.w + a1.w + a2.w + a3.w;
        float inv = 1.f / (sh_s[tid >> 3] + 1e-16f);
        float vals[4] = { r0 * inv, r1 * inv, r2 * inv, r3 * inv };
        float* dst = use_internal ? (g_x1 + (long)v * HID) : (outp + (long)v * HID);
        #pragma unroll
        for (int k = 0; k < 4; k++) {
            float val = vals[k] + bias[tid * 4 + k];
            val = (val > 0.f) ? val : (__expf(val) - 1.f);   // ELU
            dst[tid * 4 + k] = val;
        }
    }
}

// ---------------- driver ----------------
extern "C" void kernel_launch(void* const* d_in, const int* in_sizes, int n_in,
                              void* d_out, int out_size) {
    const float* x    = (const float*)d_in[0];
    const int*   ei   = (const int*)d_in[1];     // int32: JAX x64 disabled
    const float* W1   = (const float*)d_in[2];
    const float* a1s  = (const float*)d_in[3];
    const float* a1d  = (const float*)d_in[4];
    const float* b1   = (const float*)d_in[5];
    const float* W2   = (const float*)d_in[6];
    const float* a2s  = (const float*)d_in[7];
    const float* a2d  = (const float*)d_in[8];
    const float* b2   = (const float*)d_in[9];
    float* out = (float*)d_out;

    int etot = in_sizes[1] / 2;
    const int* src = ei;
    const int* dst = ei + etot;

    int eb = (etot + 255) / 256;

    // CSR by dst
    zero_counts_kernel<<<(NNODES + 256) / 256, 256>>>();
    hist_kernel<<<eb, 256>>>(dst, etot);
    scan_kernel<<<1, 1024>>>();
    scatter_kernel<<<eb, 256>>>(src, dst, etot);

    dim3 ggrid((NNODES + 127) / 128, HID / 128);

    // layer 1
    sgemm_kernel<<<ggrid, 256>>>(x, W1, NNODES, FIN, 0);
    al_kernel<<<NNODES, 256>>>(a1s, a1d);
    gat_agg_kernel<<<NNODES, 256>>>(b1, out, 1);

    // layer 2
    sgemm_kernel<<<ggrid, 256>>>(nullptr, W2, NNODES, HID, 1);
    al_kernel<<<NNODES, 256>>>(a2s, a2d);
    gat_agg_kernel<<<NNODES, 256>>>(b2, out, 0);
}

// round 5
// speedup vs baseline: 1.5281x; 1.5281x over previous
#include <cuda_runtime.h>
#include <cuda_bf16.h>
#include <cstdint>

#define NNODES   50000
#define ETOT_MAX 900000
#define HID      256
#define NHEAD    8

// ================= scratch (static device globals) =================
__device__ int   g_rowptr[NNODES + 1];
__device__ int   g_cursor[NNODES];
__device__ int   g_srcs[ETOT_MAX];
__device__ __align__(16) float g_h[NNODES * HID];    // transformed features (current layer)
__device__ __align__(16) float g_x1[NNODES * HID];   // layer-1 output
__device__ float g_als[NNODES * NHEAD];
__device__ float g_ald[NNODES * NHEAD];
// bf16 hi/lo split operands
__device__ __align__(16) __nv_bfloat16 g_amhi[NNODES * HID];
__device__ __align__(16) __nv_bfloat16 g_amlo[NNODES * HID];
__device__ __align__(16) __nv_bfloat16 g_b1hi[HID * 128];   // [n][k]
__device__ __align__(16) __nv_bfloat16 g_b1lo[HID * 128];
__device__ __align__(16) __nv_bfloat16 g_b2hi[HID * HID];   // [n][k]
__device__ __align__(16) __nv_bfloat16 g_b2lo[HID * HID];

// ================= CSR build =================
__global__ void zero_counts_kernel() {
    int i = blockIdx.x * blockDim.x + threadIdx.x;
    if (i <= NNODES) g_rowptr[i] = 0;
}
__global__ void hist_kernel(const int* __restrict__ dst, int etot) {
    int i = blockIdx.x * blockDim.x + threadIdx.x;
    if (i < etot) atomicAdd(&g_rowptr[dst[i]], 1);
}
__global__ void scan_kernel() {
    __shared__ int sh[1024];
    int t = threadIdx.x;
    int carry = 0;
    for (int base = 0; base < NNODES; base += 1024) {
        int i = base + t;
        int v = (i < NNODES) ? g_rowptr[i] : 0;
        sh[t] = v;
        __syncthreads();
        #pragma unroll
        for (int off = 1; off < 1024; off <<= 1) {
            int x = (t >= off) ? sh[t - off] : 0;
            __syncthreads();
            sh[t] += x;
            __syncthreads();
        }
        int incl = sh[t];
        int excl = incl - v + carry;
        if (i < NNODES) { g_rowptr[i] = excl; g_cursor[i] = excl; }
        carry += sh[1023];
        __syncthreads();
    }
    if (t == 0) g_rowptr[NNODES] = carry;
}
__global__ void scatter_kernel(const int* __restrict__ src,
                               const int* __restrict__ dst, int etot) {
    int i = blockIdx.x * blockDim.x + threadIdx.x;
    if (i < etot) {
        int pos = atomicAdd(&g_cursor[dst[i]], 1);
        g_srcs[pos] = src[i];
    }
}

// ================= fp32 -> bf16 hi/lo conversions =================
__global__ void convA_kernel(const float* __restrict__ A, int n) {
    int i = blockIdx.x * blockDim.x + threadIdx.x;
    if (i < n) {
        float x = A[i];
        __nv_bfloat16 h = __float2bfloat16(x);
        g_amhi[i] = h;
        g_amlo[i] = __float2bfloat16(x - __bfloat162float(h));
    }
}
// W [K][HID] row-major -> B [n][k]
__global__ void convW_kernel(const float* __restrict__ W, int K, int which) {
    __nv_bfloat16* bh = which ? g_b2hi : g_b1hi;
    __nv_bfloat16* bl = which ? g_b2lo : g_b1lo;
    int i = blockIdx.x * blockDim.x + threadIdx.x;
    if (i < K * HID) {
        int k = i / HID, n = i - k * HID;
        float x = W[i];
        __nv_bfloat16 h = __float2bfloat16(x);
        bh[n * K + k] = h;
        bl[n * K + k] = __float2bfloat16(x - __bfloat162float(h));
    }
}

// ================= bf16 mma.sync GEMM with fused attention logits =================
__device__ __forceinline__ void mma_bf16(float* c, const uint32_t* a, uint32_t b0, uint32_t b1) {
    asm volatile("mma.sync.aligned.m16n8k16.row.col.f32.bf16.bf16.f32 "
        "{%0,%1,%2,%3}, {%4,%5,%6,%7}, {%8,%9}, {%0,%1,%2,%3};"
        : "+f"(c[0]), "+f"(c[1]), "+f"(c[2]), "+f"(c[3])
        : "r"(a[0]), "r"(a[1]), "r"(a[2]), "r"(a[3]), "r"(b0), "r"(b1));
}

// C[M,256] = A[M,K] @ B[K,256]; A = g_amhi/lo, B = g_b*hi/lo (stored [n][k]).
// CTA: 128 rows x 128 cols. 8 warps: wm in {0,1} (64 rows), wn in {0..3} (32 cols = 1 head).
__global__ void __launch_bounds__(256)
gemm_mma_kernel(int layer, int M,
                const float* __restrict__ asrc, const float* __restrict__ adst) {
    const int K = layer ? 256 : 128;
    const __nv_bfloat16* __restrict__ bhi = layer ? g_b2hi : g_b1hi;
    const __nv_bfloat16* __restrict__ blo = layer ? g_b2lo : g_b1lo;

    __shared__ __nv_bfloat16 sAhi[128][40];
    __shared__ __nv_bfloat16 sAlo[128][40];
    __shared__ __nv_bfloat16 sBhi[128][40];
    __shared__ __nv_bfloat16 sBlo[128][40];

    const int tid = threadIdx.x, lane = tid & 31, wid = tid >> 5;
    const int wm = wid >> 2, wn = wid & 3;
    const int row0 = blockIdx.x * 128;
    const int n0 = blockIdx.y * 128;
    const int qid = lane >> 2, qlane = lane & 3;

    float c[4][4][4];
    #pragma unroll
    for (int i = 0; i < 4; i++)
        #pragma unroll
        for (int j = 0; j < 4; j++)
            #pragma unroll
            for (int k = 0; k < 4; k++) c[i][j][k] = 0.f;

    const int nkb = K >> 5;
    for (int kb = 0; kb < nkb; kb++) {
        // load A/B tiles: 128 rows x 32 bf16 each (hi & lo)
        #pragma unroll
        for (int i = 0; i < 4; i++) {
            int idx = tid + 256 * i;         // 0..1023
            int r = idx >> 3, kq = idx & 7;  // row, 4-bf16 quad
            int gr = row0 + r;
            uint2 vh = make_uint2(0u, 0u), vl = vh;
            if (gr < M) {
                size_t go = (size_t)gr * K + kb * 32 + kq * 4;
                vh = *(const uint2*)&g_amhi[go];
                vl = *(const uint2*)&g_amlo[go];
            }
            *(uint2*)&sAhi[r][kq * 4] = vh;
            *(uint2*)&sAlo[r][kq * 4] = vl;
            size_t gb = (size_t)(n0 + r) * K + kb * 32 + kq * 4;
            *(uint2*)&sBhi[r][kq * 4] = *(const uint2*)&bhi[gb];
            *(uint2*)&sBlo[r][kq * 4] = *(const uint2*)&blo[gb];
        }
        __syncthreads();

        #pragma unroll
        for (int ks = 0; ks < 2; ks++) {
            const int k0 = ks * 16;
            uint32_t ah[4][4], al[4][4];
            #pragma unroll
            for (int mi = 0; mi < 4; mi++) {
                int r = wm * 64 + mi * 16 + qid;
                int cw = k0 + qlane * 2;
                ah[mi][0] = *(const uint32_t*)&sAhi[r][cw];
                ah[mi][1] = *(const uint32_t*)&sAhi[r + 8][cw];
                ah[mi][2] = *(const uint32_t*)&sAhi[r][cw + 8];
                ah[mi][3] = *(const uint32_t*)&sAhi[r + 8][cw + 8];
                al[mi][0] = *(const uint32_t*)&sAlo[r][cw];
                al[mi][1] = *(const uint32_t*)&sAlo[r + 8][cw];
                al[mi][2] = *(const uint32_t*)&sAlo[r][cw + 8];
                al[mi][3] = *(const uint32_t*)&sAlo[r + 8][cw + 8];
            }
            #pragma unroll
            for (int ni = 0; ni < 4; ni++) {
                int n = wn * 32 + ni * 8 + qid;
                int kw = k0 + qlane * 2;
                uint32_t bh0 = *(const uint32_t*)&sBhi[n][kw];
                uint32_t bh1 = *(const uint32_t*)&sBhi[n][kw + 8];
                uint32_t bl0 = *(const uint32_t*)&sBlo[n][kw];
                uint32_t bl1 = *(const uint32_t*)&sBlo[n][kw + 8];
                #pragma unroll
                for (int mi = 0; mi < 4; mi++) {
                    mma_bf16(c[mi][ni], ah[mi], bh0, bh1);
                    mma_bf16(c[mi][ni], ah[mi], bl0, bl1);
                    mma_bf16(c[mi][ni], al[mi], bh0, bh1);
                }
            }
        }
        __syncthreads();
    }

    // ---- epilogue: fused attention logits (this warp's 32 cols == one head) ----
    const int head = (n0 >> 5) + wn;
    float as_v[4][2], ad_v[4][2];
    #pragma unroll
    for (int ni = 0; ni < 4; ni++)
        #pragma unroll
        for (int j = 0; j < 2; j++) {
            int col = head * 32 + ni * 8 + qlane * 2 + j;
            as_v[ni][j] = asrc[col];
            ad_v[ni][j] = adst[col];
        }
    #pragma unroll
    for (int mi = 0; mi < 4; mi++) {
        #pragma unroll
        for (int h = 0; h < 2; h++) {
            float ps = 0.f, pd = 0.f;
            #pragma unroll
            for (int ni = 0; ni < 4; ni++)
                #pragma unroll
                for (int j = 0; j < 2; j++) {
                    float v = c[mi][ni][h * 2 + j];
                    ps = fmaf(v, as_v[ni][j], ps);
                    pd = fmaf(v, ad_v[ni][j], pd);
                }
            ps += __shfl_xor_sync(0xffffffffu, ps, 1);
            ps += __shfl_xor_sync(0xffffffffu, ps, 2);
            pd += __shfl_xor_sync(0xffffffffu, pd, 1);
            pd += __shfl_xor_sync(0xffffffffu, pd, 2);
            int row = row0 + wm * 64 + mi * 16 + h * 8 + qid;
            if (qlane == 0 && row < M) {
                g_als[row * NHEAD + head] = ps;
                g_ald[row * NHEAD + head] = pd;
            }
        }
    }
    // ---- store C ----
    #pragma unroll
    for (int mi = 0; mi < 4; mi++) {
        int r = row0 + wm * 64 + mi * 16 + qid;
        #pragma unroll
        for (int ni = 0; ni < 4; ni++) {
            int cg = n0 + wn * 32 + ni * 8 + qlane * 2;
            if (r < M)
                *(float2*)&g_h[(size_t)r * HID + cg] = make_float2(c[mi][ni][0], c[mi][ni][1]);
            if (r + 8 < M)
                *(float2*)&g_h[(size_t)(r + 8) * HID + cg] = make_float2(c[mi][ni][2], c[mi][ni][3]);
        }
    }
}

// ================= segmented softmax + aggregation + bias + ELU =================
// use_internal: 1 -> write g_x1 AND bf16 hi/lo split (feeds layer-2 GEMM); 0 -> write outp
__global__ void __launch_bounds__(256)
gat_agg_kernel(const float* __restrict__ bias, float* __restrict__ outp,
               int use_internal) {
    int v = blockIdx.x;
    int tid = threadIdx.x, lane = tid & 31, warp = tid >> 5;
    int start = g_rowptr[v], end = g_rowptr[v + 1];

    __shared__ float sh_m[8], sh_s[8];
    __shared__ float sh_w[8][64];
    __shared__ int   sh_src[64];
    __shared__ float4 sh_red[256];

    float aldv = g_ald[v * NHEAD + warp];

    float m = -1e30f;
    for (int j = start + lane; j < end; j += 32) {
        int s = g_srcs[j];
        float e = g_als[s * NHEAD + warp] + aldv;
        e = (e > 0.f) ? e : 0.2f * e;
        m = fmaxf(m, e);
    }
    #pragma unroll
    for (int o = 16; o; o >>= 1) m = fmaxf(m, __shfl_xor_sync(0xffffffffu, m, o));
    if (lane == 0) sh_m[warp] = m;
    __syncthreads();
    m = sh_m[warp];

    float ssum = 0.f;
    float4 acc = make_float4(0.f, 0.f, 0.f, 0.f);
    int cg = tid & 63;
    int sub = tid >> 6;
    int headc = cg >> 3;

    for (int t = start; t < end; t += 64) {
        int cnt = min(64, end - t);
        for (int j = lane; j < cnt; j += 32) {
            int s = g_srcs[t + j];
            if (warp == 0) sh_src[j] = s;
            float e = g_als[s * NHEAD + warp] + aldv;
            e = (e > 0.f) ? e : 0.2f * e;
            float w = __expf(e - m);
            sh_w[warp][j] = w;
            ssum += w;
        }
        __syncthreads();
        for (int j = sub; j < cnt; j += 4) {
            int s = sh_src[j];
            float w = sh_w[headc][j];
            const float4 hv = *reinterpret_cast<const float4*>(&g_h[(size_t)s * HID + cg * 4]);
            acc.x = fmaf(w, hv.x, acc.x);
            acc.y = fmaf(w, hv.y, acc.y);
            acc.z = fmaf(w, hv.z, acc.z);
            acc.w = fmaf(w, hv.w, acc.w);
        }
        __syncthreads();
    }

    #pragma unroll
    for (int o = 16; o; o >>= 1) ssum += __shfl_xor_sync(0xffffffffu, ssum, o);
    if (lane == 0) sh_s[warp] = ssum;

    sh_red[tid] = acc;
    __syncthreads();

    if (tid < 64) {
        float4 a0 = sh_red[tid];
        float4 a1 = sh_red[tid + 64];
        float4 a2 = sh_red[tid + 128];
        float4 a3 = sh_red[tid + 192];
        float r0 = a0.x + a1.x + a2.x + a3.x;
        float r1 = a0.y + a1.y + a2.y + a3.y;
        float r2 = a0.z + a1.z + a2.z + a3.z;
        float r3 = a0.w + a1.w + a2.w + a3.w;
        float inv = 1.f / (sh_s[tid >> 3] + 1e-16f);
        float vals[4] = { r0 * inv, r1 * inv, r2 * inv, r3 * inv };
        #pragma unroll
        for (int k = 0; k < 4; k++) {
            float val = vals[k] + bias[tid * 4 + k];
            val = (val > 0.f) ? val : (__expf(val) - 1.f);
            size_t idx = (size_t)v * HID + tid * 4 + k;
            if (use_internal) {
                g_x1[idx] = val;
                __nv_bfloat16 hb = __float2bfloat16(val);
                g_amhi[idx] = hb;
                g_amlo[idx] = __float2bfloat16(val - __bfloat162float(hb));
            } else {
                outp[idx] = val;
            }
        }
    }
}

// ================= driver =================
extern "C" void kernel_launch(void* const* d_in, const int* in_sizes, int n_in,
                              void* d_out, int out_size) {
    const float* x    = (const float*)d_in[0];
    const int*   ei   = (const int*)d_in[1];
    const float* W1   = (const float*)d_in[2];
    const float* a1s  = (const float*)d_in[3];
    const float* a1d  = (const float*)d_in[4];
    const float* b1   = (const float*)d_in[5];
    const float* W2   = (const float*)d_in[6];
    const float* a2s  = (const float*)d_in[7];
    const float* a2d  = (const float*)d_in[8];
    const float* b2   = (const float*)d_in[9];
    float* out = (float*)d_out;

    int etot = in_sizes[1] / 2;
    const int* src = ei;
    const int* dst = ei + etot;
    int eb = (etot + 255) / 256;

    // CSR by dst
    zero_counts_kernel<<<(NNODES + 256) / 256, 256>>>();
    hist_kernel<<<eb, 256>>>(dst, etot);
    scan_kernel<<<1, 1024>>>();
    scatter_kernel<<<eb, 256>>>(src, dst, etot);

    // weight splits
    convW_kernel<<<(128 * HID + 255) / 256, 256>>>(W1, 128, 0);
    convW_kernel<<<(HID * HID + 255) / 256, 256>>>(W2, HID, 1);

    dim3 ggrid((NNODES + 127) / 128, 2);

    // layer 1
    convA_kernel<<<(NNODES * 128 + 255) / 256, 256>>>(x, NNODES * 128);
    gemm_mma_kernel<<<ggrid, 256>>>(0, NNODES, a1s, a1d);
    gat_agg_kernel<<<NNODES, 256>>>(b1, out, 1);

    // layer 2 (bf16 split of g_x1 already produced by layer-1 agg epilogue)
    gemm_mma_kernel<<<ggrid, 256>>>(1, NNODES, a2s, a2d);
    gat_agg_kernel<<<NNODES, 256>>>(b2, out, 0);
}